// round 1
// baseline (speedup 1.0000x reference)
#include <cuda_runtime.h>
#include <math.h>

// ---------------- problem constants ----------------
#define B_WIN   4096
#define NTOK    64
#define CDIM    512
#define NHEAD   16
#define HDIM    32
#define MTOT    (B_WIN * NTOK)      // 262144 rows
#define QKV_N   1536
#define NUM_WIN 256

// ---------------- scratch (static device globals; no allocation) ----------------
__device__ float g_qkv[402653184];   // [MTOT, 1536]  = 1.61 GB
__device__ float g_attn[134217728];  // [MTOT, 512]   = 512 MB
__device__ float g_bias[NHEAD * NTOK * NTOK];  // [16,64,64]
__device__ float g_qkvbias[QKV_N];

// ---------------- tiny setup kernels ----------------
__global__ void qkvbias_kernel(const float* __restrict__ q_bias,
                               const float* __restrict__ v_bias,
                               float* __restrict__ out) {
    int i = blockIdx.x * blockDim.x + threadIdx.x;
    if (i >= QKV_N) return;
    float v;
    if (i < 512)       v = q_bias[i];
    else if (i < 1024) v = 0.0f;
    else               v = v_bias[i - 1024];
    out[i] = v;
}

__device__ __forceinline__ float cpb_coord(int x) {
    // t = x/7 * 8 ; sign(t)*log2(|t|+1)/log2(8)
    float t = (float)x * (8.0f / 7.0f);
    float m = log2f(fabsf(t) + 1.0f) * (1.0f / 3.0f);
    return (t > 0.0f) ? m : ((t < 0.0f) ? -m : 0.0f);
}

// grid(16 heads), block(256): CPB MLP -> sigmoid table -> scatter by rel idx
__global__ void cpb_bias_kernel(const float* __restrict__ w1,  // [512,2]
                                const float* __restrict__ b1,  // [512]
                                const float* __restrict__ w2,  // [16,512]
                                float* __restrict__ bias_out)  // [16,64,64]
{
    __shared__ float tableh[225];
    int h = blockIdx.x;
    int tid = threadIdx.x;
    for (int tt = tid; tt < 225; tt += blockDim.x) {
        int ih = tt / 15, iw = tt % 15;
        float t0 = cpb_coord(ih - 7);
        float t1 = cpb_coord(iw - 7);
        float val = 0.0f;
        for (int j = 0; j < 512; j++) {
            float hj = w1[2 * j] * t0 + w1[2 * j + 1] * t1 + b1[j];
            hj = fmaxf(hj, 0.0f);
            val += hj * w2[h * 512 + j];
        }
        tableh[tt] = 16.0f / (1.0f + expf(-val));
    }
    __syncthreads();
    for (int e = tid; e < NTOK * NTOK; e += blockDim.x) {
        int i = e >> 6, j = e & 63;
        int dh = (i >> 3) - (j >> 3) + 7;
        int dw = (i & 7) - (j & 7) + 7;
        bias_out[h * 4096 + e] = tableh[dh * 15 + dw];
    }
}

// ---------------- SGEMM: C[M,N] = A[M,K] @ B[N,K]^T + bias[N] ----------------
// 128x128 tile, BK=16, 256 threads, 8x8 per-thread register block.
// M,N,K all multiples of 128 here -> no bounds checks.
#define BM 128
#define BN 128
#define BK 16

__global__ __launch_bounds__(256)
void sgemm_bias_kernel(const float* __restrict__ A,
                       const float* __restrict__ B,
                       const float* __restrict__ bias,
                       float* __restrict__ C,
                       int M, int N, int K)
{
    __shared__ float As[BK][BM];
    __shared__ float Bs[BK][BN];

    const int tid = threadIdx.x;
    const int bm = blockIdx.y * BM;
    const int bn = blockIdx.x * BN;

    const int lr = tid >> 2;          // 0..63 (load row)
    const int lc = (tid & 3) * 4;     // 0,4,8,12 (k offset)

    const int m0 = (tid >> 4) * 8;    // 0..120
    const int n0 = (tid & 15) * 8;

    float acc[8][8];
#pragma unroll
    for (int i = 0; i < 8; i++)
#pragma unroll
        for (int j = 0; j < 8; j++) acc[i][j] = 0.0f;

    for (int k0 = 0; k0 < K; k0 += BK) {
#pragma unroll
        for (int p = 0; p < 2; p++) {
            int row = lr + p * 64;
            float4 va = *(const float4*)&A[(bm + row) * K + k0 + lc];
            As[lc + 0][row] = va.x; As[lc + 1][row] = va.y;
            As[lc + 2][row] = va.z; As[lc + 3][row] = va.w;
            float4 vb = *(const float4*)&B[(bn + row) * K + k0 + lc];
            Bs[lc + 0][row] = vb.x; Bs[lc + 1][row] = vb.y;
            Bs[lc + 2][row] = vb.z; Bs[lc + 3][row] = vb.w;
        }
        __syncthreads();

#pragma unroll
        for (int kk = 0; kk < BK; kk++) {
            float4 a0 = *(const float4*)&As[kk][m0];
            float4 a1 = *(const float4*)&As[kk][m0 + 4];
            float4 b0 = *(const float4*)&Bs[kk][n0];
            float4 b1 = *(const float4*)&Bs[kk][n0 + 4];
            float af[8] = {a0.x, a0.y, a0.z, a0.w, a1.x, a1.y, a1.z, a1.w};
            float bf[8] = {b0.x, b0.y, b0.z, b0.w, b1.x, b1.y, b1.z, b1.w};
#pragma unroll
            for (int i = 0; i < 8; i++)
#pragma unroll
                for (int j = 0; j < 8; j++)
                    acc[i][j] = fmaf(af[i], bf[j], acc[i][j]);
        }
        __syncthreads();
    }

    float4 bb0 = *(const float4*)&bias[bn + n0];
    float4 bb1 = *(const float4*)&bias[bn + n0 + 4];
    float bf[8] = {bb0.x, bb0.y, bb0.z, bb0.w, bb1.x, bb1.y, bb1.z, bb1.w};
#pragma unroll
    for (int i = 0; i < 8; i++) {
        float4 o0, o1;
        o0.x = acc[i][0] + bf[0]; o0.y = acc[i][1] + bf[1];
        o0.z = acc[i][2] + bf[2]; o0.w = acc[i][3] + bf[3];
        o1.x = acc[i][4] + bf[4]; o1.y = acc[i][5] + bf[5];
        o1.z = acc[i][6] + bf[6]; o1.w = acc[i][7] + bf[7];
        *(float4*)&C[(bm + m0 + i) * N + bn + n0]     = o0;
        *(float4*)&C[(bm + m0 + i) * N + bn + n0 + 4] = o1;
    }
}

// ---------------- fused cosine attention per (window, head) ----------------
// grid(4096, 16), block(256)
__global__ __launch_bounds__(256)
void attn_kernel(const float* __restrict__ qkv,       // [MTOT, 1536]
                 const float* __restrict__ mask,      // [256, 64, 64]
                 const float* __restrict__ logit_scale, // [16]
                 const float* __restrict__ bias,      // [16, 64, 64]
                 float* __restrict__ out)             // [MTOT, 512]
{
    __shared__ float qs[NTOK][HDIM + 1];
    __shared__ float ks[NTOK][HDIM + 1];
    __shared__ float vs[NTOK][HDIM + 1];
    __shared__ float S[NTOK][NTOK + 1];

    const int w = blockIdx.x;
    const int h = blockIdx.y;
    const int tid = threadIdx.x;

    const float* base = qkv + (size_t)w * NTOK * QKV_N + h * HDIM;

    // load q,k,v tiles (vectorized)
    for (int idx = tid; idx < NTOK * HDIM / 4; idx += 256) {
        int n = idx >> 3;
        int d = (idx & 7) * 4;
        const float* r = base + n * QKV_N + d;
        float4 q4 = *(const float4*)(r);
        float4 k4 = *(const float4*)(r + 512);
        float4 v4 = *(const float4*)(r + 1024);
        qs[n][d] = q4.x; qs[n][d + 1] = q4.y; qs[n][d + 2] = q4.z; qs[n][d + 3] = q4.w;
        ks[n][d] = k4.x; ks[n][d + 1] = k4.y; ks[n][d + 2] = k4.z; ks[n][d + 3] = k4.w;
        vs[n][d] = v4.x; vs[n][d + 1] = v4.y; vs[n][d + 2] = v4.z; vs[n][d + 3] = v4.w;
    }
    __syncthreads();

    // normalize rows; fold logit-scale factor into q
    const float scale = expf(fminf(logit_scale[h], 4.605170186f)); // ln(100)
    if (tid < 128) {
        int r = tid & 63;
        float* row = (tid < 64) ? qs[r] : ks[r];
        float ss = 0.0f;
#pragma unroll
        for (int d = 0; d < HDIM; d++) ss += row[d] * row[d];
        float rn = rsqrtf(ss);
        if (tid < 64) rn *= scale;
#pragma unroll
        for (int d = 0; d < HDIM; d++) row[d] *= rn;
    }
    __syncthreads();

    // S = qn @ kn^T + bias[h] + mask[w % 256]
    {
        const int i = tid >> 2;
        const int jb = (tid & 3) * 16;
        const float* bh = bias + h * 4096 + i * 64;
        const float* mh = mask + (size_t)(w & (NUM_WIN - 1)) * 4096 + i * 64;
#pragma unroll
        for (int j = 0; j < 16; j++) {
            float dot = 0.0f;
#pragma unroll
            for (int d = 0; d < HDIM; d++) dot = fmaf(qs[i][d], ks[jb + j][d], dot);
            S[i][jb + j] = dot + bh[jb + j] + mh[jb + j];
        }
    }
    __syncthreads();

    // softmax rows (one thread per row)
    if (tid < NTOK) {
        float mx = -1e30f;
#pragma unroll
        for (int j = 0; j < NTOK; j++) mx = fmaxf(mx, S[tid][j]);
        float sum = 0.0f;
#pragma unroll
        for (int j = 0; j < NTOK; j++) {
            float e = expf(S[tid][j] - mx);
            S[tid][j] = e;
            sum += e;
        }
        float inv = 1.0f / sum;
#pragma unroll
        for (int j = 0; j < NTOK; j++) S[tid][j] *= inv;
    }
    __syncthreads();

    // O = S @ V, write [w*64+i, h*32 + d]
    {
        const int i = tid >> 2;
        const int db = (tid & 3) * 8;
        float o[8];
#pragma unroll
        for (int d = 0; d < 8; d++) o[d] = 0.0f;
#pragma unroll
        for (int m = 0; m < NTOK; m++) {
            float s = S[i][m];
#pragma unroll
            for (int d = 0; d < 8; d++) o[d] = fmaf(s, vs[m][db + d], o[d]);
        }
        float* op = out + (size_t)(w * NTOK + i) * CDIM + h * HDIM + db;
        float4 o0 = {o[0], o[1], o[2], o[3]};
        float4 o1 = {o[4], o[5], o[6], o[7]};
        *(float4*)(op)     = o0;
        *(float4*)(op + 4) = o1;
    }
}

// ---------------- launch ----------------
extern "C" void kernel_launch(void* const* d_in, const int* in_sizes, int n_in,
                              void* d_out, int out_size)
{
    const float* x           = (const float*)d_in[0];
    const float* mask        = (const float*)d_in[1];
    const float* qkv_w       = (const float*)d_in[2];
    const float* q_bias      = (const float*)d_in[3];
    const float* v_bias      = (const float*)d_in[4];
    const float* logit_scale = (const float*)d_in[5];
    const float* cpb_w1      = (const float*)d_in[6];
    const float* cpb_b1      = (const float*)d_in[7];
    const float* cpb_w2      = (const float*)d_in[8];
    const float* proj_w      = (const float*)d_in[9];
    const float* proj_b      = (const float*)d_in[10];
    float* out = (float*)d_out;

    float *qkv_buf, *attn_buf, *bias_buf, *qb_buf;
    cudaGetSymbolAddress((void**)&qkv_buf, g_qkv);
    cudaGetSymbolAddress((void**)&attn_buf, g_attn);
    cudaGetSymbolAddress((void**)&bias_buf, g_bias);
    cudaGetSymbolAddress((void**)&qb_buf, g_qkvbias);

    qkvbias_kernel<<<(QKV_N + 255) / 256, 256>>>(q_bias, v_bias, qb_buf);
    cpb_bias_kernel<<<NHEAD, 256>>>(cpb_w1, cpb_b1, cpb_w2, bias_buf);

    // QKV projection: [262144,512] @ [1536,512]^T
    {
        dim3 grid(QKV_N / BN, MTOT / BM);
        sgemm_bias_kernel<<<grid, 256>>>(x, qkv_w, qb_buf, qkv_buf,
                                         MTOT, QKV_N, CDIM);
    }

    // attention
    {
        dim3 grid(B_WIN, NHEAD);
        attn_kernel<<<grid, 256>>>(qkv_buf, mask, logit_scale, bias_buf, attn_buf);
    }

    // output projection: [262144,512] @ [512,512]^T -> d_out
    {
        dim3 grid(CDIM / BN, MTOT / BM);
        sgemm_bias_kernel<<<grid, 256>>>(attn_buf, proj_w, proj_b, out,
                                         MTOT, CDIM, CDIM);
    }
}

// round 2
// speedup vs baseline: 1.9179x; 1.9179x over previous
#include <cuda_runtime.h>
#include <math.h>
#include <stdint.h>

// ---------------- problem constants ----------------
#define B_WIN   4096
#define NTOK    64
#define CDIM    512
#define NHEAD   16
#define HDIM    32
#define MTOT    (B_WIN * NTOK)      // 262144 rows
#define QKV_N   1536
#define NUM_WIN 256

// ---------------- scratch (static device globals; no allocation) ----------------
__device__ float g_qkv[402653184];   // [MTOT, 1536]  = 1.61 GB
__device__ float g_attn[134217728];  // [MTOT, 512]   = 512 MB
__device__ float g_bias[NHEAD * NTOK * NTOK];  // [16,64,64]
__device__ float g_qkvbias[QKV_N];

// ---------------- tiny setup kernels ----------------
__global__ void qkvbias_kernel(const float* __restrict__ q_bias,
                               const float* __restrict__ v_bias,
                               float* __restrict__ out) {
    int i = blockIdx.x * blockDim.x + threadIdx.x;
    if (i >= QKV_N) return;
    float v;
    if (i < 512)       v = q_bias[i];
    else if (i < 1024) v = 0.0f;
    else               v = v_bias[i - 1024];
    out[i] = v;
}

__device__ __forceinline__ float cpb_coord(int x) {
    float t = (float)x * (8.0f / 7.0f);
    float m = log2f(fabsf(t) + 1.0f) * (1.0f / 3.0f);
    return (t > 0.0f) ? m : ((t < 0.0f) ? -m : 0.0f);
}

__global__ void cpb_bias_kernel(const float* __restrict__ w1,  // [512,2]
                                const float* __restrict__ b1,  // [512]
                                const float* __restrict__ w2,  // [16,512]
                                float* __restrict__ bias_out)  // [16,64,64]
{
    __shared__ float tableh[225];
    int h = blockIdx.x;
    int tid = threadIdx.x;
    for (int tt = tid; tt < 225; tt += blockDim.x) {
        int ih = tt / 15, iw = tt % 15;
        float t0 = cpb_coord(ih - 7);
        float t1 = cpb_coord(iw - 7);
        float val = 0.0f;
        for (int j = 0; j < 512; j++) {
            float hj = w1[2 * j] * t0 + w1[2 * j + 1] * t1 + b1[j];
            hj = fmaxf(hj, 0.0f);
            val += hj * w2[h * 512 + j];
        }
        tableh[tt] = 16.0f / (1.0f + expf(-val));
    }
    __syncthreads();
    for (int e = tid; e < NTOK * NTOK; e += blockDim.x) {
        int i = e >> 6, j = e & 63;
        int dh = (i >> 3) - (j >> 3) + 7;
        int dw = (i & 7) - (j & 7) + 7;
        bias_out[h * 4096 + e] = tableh[dh * 15 + dw];
    }
}

// ---------------- tf32 tensor-core GEMM ----------------
// C[M,N] = A[M,K] @ B[N,K]^T + bias[N]
// 128x128 block tile, BK=16, 256 threads (8 warps, 2x4), 64x32 warp tile.
// mma.sync.aligned.m16n8k8.row.col.f32.tf32.tf32.f32

#define BM 128
#define BN 128
#define BK 16
#define SPAD 20   // smem row stride (conflict-free for fragment LDS pattern)

__device__ __forceinline__ uint32_t f2tf32(float f) {
    uint32_t u;
    asm("cvt.rna.tf32.f32 %0, %1;" : "=r"(u) : "f"(f));
    return u;
}

__device__ __forceinline__ void mma_tf32(float* c, const uint32_t* a, const uint32_t* b) {
    asm volatile(
        "mma.sync.aligned.m16n8k8.row.col.f32.tf32.tf32.f32 "
        "{%0,%1,%2,%3}, {%4,%5,%6,%7}, {%8,%9}, {%0,%1,%2,%3};"
        : "+f"(c[0]), "+f"(c[1]), "+f"(c[2]), "+f"(c[3])
        : "r"(a[0]), "r"(a[1]), "r"(a[2]), "r"(a[3]), "r"(b[0]), "r"(b[1]));
}

__global__ __launch_bounds__(256)
void mma_gemm_bias(const float* __restrict__ A,
                   const float* __restrict__ B,
                   const float* __restrict__ bias,
                   float* __restrict__ C,
                   int M, int N, int K)
{
    __shared__ uint32_t As[BM][SPAD];
    __shared__ uint32_t Bs[BN][SPAD];

    const int tid  = threadIdx.x;
    const int wid  = tid >> 5;
    const int lane = tid & 31;
    const int g    = lane >> 2;   // groupID 0..7
    const int t    = lane & 3;    // threadID_in_group 0..3

    const int wm = (wid >> 2) * 64;   // warp m offset (0 or 64)
    const int wn = (wid & 3) * 32;    // warp n offset (0,32,64,96)

    const int bm = blockIdx.y * BM;
    const int bn = blockIdx.x * BN;

    const int lr = tid >> 2;          // load row 0..63
    const int lc = (tid & 3) * 4;     // k offset 0,4,8,12

    float acc[4][4][4];
#pragma unroll
    for (int i = 0; i < 4; i++)
#pragma unroll
        for (int j = 0; j < 4; j++)
#pragma unroll
            for (int r = 0; r < 4; r++) acc[i][j][r] = 0.0f;

    for (int k0 = 0; k0 < K; k0 += BK) {
#pragma unroll
        for (int p = 0; p < 2; p++) {
            int row = lr + p * 64;
            float4 va = *(const float4*)&A[(size_t)(bm + row) * K + k0 + lc];
            uint4 ua = {f2tf32(va.x), f2tf32(va.y), f2tf32(va.z), f2tf32(va.w)};
            *(uint4*)&As[row][lc] = ua;
            float4 vb = *(const float4*)&B[(size_t)(bn + row) * K + k0 + lc];
            uint4 ub = {f2tf32(vb.x), f2tf32(vb.y), f2tf32(vb.z), f2tf32(vb.w)};
            *(uint4*)&Bs[row][lc] = ub;
        }
        __syncthreads();

#pragma unroll
        for (int ks = 0; ks < BK; ks += 8) {
            uint32_t af[4][4];
#pragma unroll
            for (int mf = 0; mf < 4; mf++) {
                int rb = wm + mf * 16;
                af[mf][0] = As[rb + g][ks + t];
                af[mf][1] = As[rb + g + 8][ks + t];
                af[mf][2] = As[rb + g][ks + t + 4];
                af[mf][3] = As[rb + g + 8][ks + t + 4];
            }
            uint32_t bf[4][2];
#pragma unroll
            for (int nf = 0; nf < 4; nf++) {
                int rb = wn + nf * 8;
                bf[nf][0] = Bs[rb + g][ks + t];
                bf[nf][1] = Bs[rb + g][ks + t + 4];
            }
#pragma unroll
            for (int mf = 0; mf < 4; mf++)
#pragma unroll
                for (int nf = 0; nf < 4; nf++)
                    mma_tf32(acc[mf][nf], af[mf], bf[nf]);
        }
        __syncthreads();
    }

    // epilogue: add bias, store
#pragma unroll
    for (int mf = 0; mf < 4; mf++) {
#pragma unroll
        for (int nf = 0; nf < 4; nf++) {
            int row0 = bm + wm + mf * 16 + g;
            int col  = bn + wn + nf * 8 + 2 * t;
            float b0 = bias[col], b1 = bias[col + 1];
            float2 o0 = {acc[mf][nf][0] + b0, acc[mf][nf][1] + b1};
            float2 o1 = {acc[mf][nf][2] + b0, acc[mf][nf][3] + b1};
            *(float2*)&C[(size_t)row0 * N + col]       = o0;
            *(float2*)&C[(size_t)(row0 + 8) * N + col] = o1;
        }
    }
}

// ---------------- fused cosine attention per (window, head) ----------------
__global__ __launch_bounds__(256)
void attn_kernel(const float* __restrict__ qkv,       // [MTOT, 1536]
                 const float* __restrict__ mask,      // [256, 64, 64]
                 const float* __restrict__ logit_scale, // [16]
                 const float* __restrict__ bias,      // [16, 64, 64]
                 float* __restrict__ out)             // [MTOT, 512]
{
    __shared__ float qs[NTOK][HDIM + 1];
    __shared__ float ks[NTOK][HDIM + 1];
    __shared__ float vs[NTOK][HDIM + 1];
    __shared__ float S[NTOK][NTOK + 1];

    const int w = blockIdx.x;
    const int h = blockIdx.y;
    const int tid = threadIdx.x;

    const float* base = qkv + (size_t)w * NTOK * QKV_N + h * HDIM;

    for (int idx = tid; idx < NTOK * HDIM / 4; idx += 256) {
        int n = idx >> 3;
        int d = (idx & 7) * 4;
        const float* r = base + n * QKV_N + d;
        float4 q4 = *(const float4*)(r);
        float4 k4 = *(const float4*)(r + 512);
        float4 v4 = *(const float4*)(r + 1024);
        qs[n][d] = q4.x; qs[n][d + 1] = q4.y; qs[n][d + 2] = q4.z; qs[n][d + 3] = q4.w;
        ks[n][d] = k4.x; ks[n][d + 1] = k4.y; ks[n][d + 2] = k4.z; ks[n][d + 3] = k4.w;
        vs[n][d] = v4.x; vs[n][d + 1] = v4.y; vs[n][d + 2] = v4.z; vs[n][d + 3] = v4.w;
    }
    __syncthreads();

    const float scale = expf(fminf(logit_scale[h], 4.605170186f)); // ln(100)
    if (tid < 128) {
        int r = tid & 63;
        float* row = (tid < 64) ? qs[r] : ks[r];
        float ss = 0.0f;
#pragma unroll
        for (int d = 0; d < HDIM; d++) ss += row[d] * row[d];
        float rn = rsqrtf(ss);
        if (tid < 64) rn *= scale;
#pragma unroll
        for (int d = 0; d < HDIM; d++) row[d] *= rn;
    }
    __syncthreads();

    {
        const int i = tid >> 2;
        const int jb = (tid & 3) * 16;
        const float* bh = bias + h * 4096 + i * 64;
        const float* mh = mask + (size_t)(w & (NUM_WIN - 1)) * 4096 + i * 64;
#pragma unroll
        for (int j = 0; j < 16; j++) {
            float dot = 0.0f;
#pragma unroll
            for (int d = 0; d < HDIM; d++) dot = fmaf(qs[i][d], ks[jb + j][d], dot);
            S[i][jb + j] = dot + bh[jb + j] + mh[jb + j];
        }
    }
    __syncthreads();

    if (tid < NTOK) {
        float mx = -1e30f;
#pragma unroll
        for (int j = 0; j < NTOK; j++) mx = fmaxf(mx, S[tid][j]);
        float sum = 0.0f;
#pragma unroll
        for (int j = 0; j < NTOK; j++) {
            float e = expf(S[tid][j] - mx);
            S[tid][j] = e;
            sum += e;
        }
        float inv = 1.0f / sum;
#pragma unroll
        for (int j = 0; j < NTOK; j++) S[tid][j] *= inv;
    }
    __syncthreads();

    {
        const int i = tid >> 2;
        const int db = (tid & 3) * 8;
        float o[8];
#pragma unroll
        for (int d = 0; d < 8; d++) o[d] = 0.0f;
#pragma unroll
        for (int m = 0; m < NTOK; m++) {
            float s = S[i][m];
#pragma unroll
            for (int d = 0; d < 8; d++) o[d] = fmaf(s, vs[m][db + d], o[d]);
        }
        float* op = out + (size_t)(w * NTOK + i) * CDIM + h * HDIM + db;
        float4 o0 = {o[0], o[1], o[2], o[3]};
        float4 o1 = {o[4], o[5], o[6], o[7]};
        *(float4*)(op)     = o0;
        *(float4*)(op + 4) = o1;
    }
}

// ---------------- launch ----------------
extern "C" void kernel_launch(void* const* d_in, const int* in_sizes, int n_in,
                              void* d_out, int out_size)
{
    const float* x           = (const float*)d_in[0];
    const float* mask        = (const float*)d_in[1];
    const float* qkv_w       = (const float*)d_in[2];
    const float* q_bias      = (const float*)d_in[3];
    const float* v_bias      = (const float*)d_in[4];
    const float* logit_scale = (const float*)d_in[5];
    const float* cpb_w1      = (const float*)d_in[6];
    const float* cpb_b1      = (const float*)d_in[7];
    const float* cpb_w2      = (const float*)d_in[8];
    const float* proj_w      = (const float*)d_in[9];
    const float* proj_b      = (const float*)d_in[10];
    float* out = (float*)d_out;

    float *qkv_buf, *attn_buf, *bias_buf, *qb_buf;
    cudaGetSymbolAddress((void**)&qkv_buf, g_qkv);
    cudaGetSymbolAddress((void**)&attn_buf, g_attn);
    cudaGetSymbolAddress((void**)&bias_buf, g_bias);
    cudaGetSymbolAddress((void**)&qb_buf, g_qkvbias);

    qkvbias_kernel<<<(QKV_N + 255) / 256, 256>>>(q_bias, v_bias, qb_buf);
    cpb_bias_kernel<<<NHEAD, 256>>>(cpb_w1, cpb_b1, cpb_w2, bias_buf);

    // QKV projection: [262144,512] @ [1536,512]^T
    {
        dim3 grid(QKV_N / BN, MTOT / BM);
        mma_gemm_bias<<<grid, 256>>>(x, qkv_w, qb_buf, qkv_buf,
                                     MTOT, QKV_N, CDIM);
    }

    // attention
    {
        dim3 grid(B_WIN, NHEAD);
        attn_kernel<<<grid, 256>>>(qkv_buf, mask, logit_scale, bias_buf, attn_buf);
    }

    // output projection: [262144,512] @ [512,512]^T -> d_out
    {
        dim3 grid(CDIM / BN, MTOT / BM);
        mma_gemm_bias<<<grid, 256>>>(attn_buf, proj_w, proj_b, out,
                                     MTOT, CDIM, CDIM);
    }
}

// round 3
// speedup vs baseline: 2.0709x; 1.0797x over previous
#include <cuda_runtime.h>
#include <math.h>
#include <stdint.h>

// ---------------- problem constants ----------------
#define B_WIN   4096
#define NTOK    64
#define CDIM    512
#define NHEAD   16
#define HDIM    32
#define MTOT    (B_WIN * NTOK)      // 262144 rows
#define QKV_N   1536
#define NUM_WIN 256

// ---------------- scratch (static device globals; no allocation) ----------------
__device__ float g_qkv[402653184];   // [MTOT, 1536]  = 1.61 GB
__device__ float g_attn[134217728];  // [MTOT, 512]   = 512 MB
__device__ float g_bias[NHEAD * NTOK * NTOK];  // [16,64,64]
__device__ float g_qkvbias[QKV_N];

// ---------------- tiny setup kernels ----------------
__global__ void qkvbias_kernel(const float* __restrict__ q_bias,
                               const float* __restrict__ v_bias,
                               float* __restrict__ out) {
    int i = blockIdx.x * blockDim.x + threadIdx.x;
    if (i >= QKV_N) return;
    float v;
    if (i < 512)       v = q_bias[i];
    else if (i < 1024) v = 0.0f;
    else               v = v_bias[i - 1024];
    out[i] = v;
}

__device__ __forceinline__ float cpb_coord(int x) {
    float t = (float)x * (8.0f / 7.0f);
    float m = log2f(fabsf(t) + 1.0f) * (1.0f / 3.0f);
    return (t > 0.0f) ? m : ((t < 0.0f) ? -m : 0.0f);
}

__global__ void cpb_bias_kernel(const float* __restrict__ w1,  // [512,2]
                                const float* __restrict__ b1,  // [512]
                                const float* __restrict__ w2,  // [16,512]
                                float* __restrict__ bias_out)  // [16,64,64]
{
    __shared__ float tableh[225];
    int h = blockIdx.x;
    int tid = threadIdx.x;
    for (int tt = tid; tt < 225; tt += blockDim.x) {
        int ih = tt / 15, iw = tt % 15;
        float t0 = cpb_coord(ih - 7);
        float t1 = cpb_coord(iw - 7);
        float val = 0.0f;
        for (int j = 0; j < 512; j++) {
            float hj = w1[2 * j] * t0 + w1[2 * j + 1] * t1 + b1[j];
            hj = fmaxf(hj, 0.0f);
            val += hj * w2[h * 512 + j];
        }
        tableh[tt] = 16.0f / (1.0f + expf(-val));
    }
    __syncthreads();
    for (int e = tid; e < NTOK * NTOK; e += blockDim.x) {
        int i = e >> 6, j = e & 63;
        int dh = (i >> 3) - (j >> 3) + 7;
        int dw = (i & 7) - (j & 7) + 7;
        bias_out[h * 4096 + e] = tableh[dh * 15 + dw];
    }
}

// ---------------- tf32 tensor-core GEMM, cp.async double-buffered ----------------
// C[M,N] = A[M,K] @ B[N,K]^T + bias[N]
// 128x128 block tile, BK=16, 256 threads (8 warps, 2x4), 64x32 warp tile.

#define BM 128
#define BN 128
#define BK 16
#define SPAD 20   // smem row stride in floats (bank-conflict-free fragment LDS)

__device__ __forceinline__ uint32_t f2tf32(float f) {
    uint32_t u;
    asm("cvt.rna.tf32.f32 %0, %1;" : "=r"(u) : "f"(f));
    return u;
}

__device__ __forceinline__ void mma_tf32(float* c, const uint32_t* a, const uint32_t* b) {
    asm volatile(
        "mma.sync.aligned.m16n8k8.row.col.f32.tf32.tf32.f32 "
        "{%0,%1,%2,%3}, {%4,%5,%6,%7}, {%8,%9}, {%0,%1,%2,%3};"
        : "+f"(c[0]), "+f"(c[1]), "+f"(c[2]), "+f"(c[3])
        : "r"(a[0]), "r"(a[1]), "r"(a[2]), "r"(a[3]), "r"(b[0]), "r"(b[1]));
}

__device__ __forceinline__ void cp16(void* smem, const void* g) {
    uint32_t s = (uint32_t)__cvta_generic_to_shared(smem);
    asm volatile("cp.async.cg.shared.global [%0], [%1], 16;" :: "r"(s), "l"(g));
}

__global__ __launch_bounds__(256)
void mma_gemm_bias(const float* __restrict__ A,
                   const float* __restrict__ B,
                   const float* __restrict__ bias,
                   float* __restrict__ C,
                   int M, int N, int K)
{
    __shared__ float As[2][BM][SPAD];   // 20.5 KB
    __shared__ float Bs[2][BN][SPAD];   // 20.5 KB

    const int tid  = threadIdx.x;
    const int wid  = tid >> 5;
    const int lane = tid & 31;
    const int g    = lane >> 2;   // groupID 0..7
    const int t    = lane & 3;    // threadID_in_group 0..3

    const int wm = (wid >> 2) * 64;   // warp m offset (0 or 64)
    const int wn = (wid & 3) * 32;    // warp n offset (0,32,64,96)

    const int bm = blockIdx.y * BM;
    const int bn = blockIdx.x * BN;

    const int lrow = tid >> 2;        // 0..63
    const int lc4  = (tid & 3) * 4;   // k float offset 0,4,8,12

    const float* Abase = A + (size_t)bm * K;
    const float* Bbase = B + (size_t)bn * K;

    float acc[4][4][4];
#pragma unroll
    for (int i = 0; i < 4; i++)
#pragma unroll
        for (int j = 0; j < 4; j++)
#pragma unroll
            for (int r = 0; r < 4; r++) acc[i][j][r] = 0.0f;

    const int NIT = K / BK;

    // issue loads for a stage
    auto issue = [&](int s, int k0) {
        cp16(&As[s][lrow][lc4],      &Abase[(size_t)lrow * K + k0 + lc4]);
        cp16(&As[s][lrow + 64][lc4], &Abase[(size_t)(lrow + 64) * K + k0 + lc4]);
        cp16(&Bs[s][lrow][lc4],      &Bbase[(size_t)lrow * K + k0 + lc4]);
        cp16(&Bs[s][lrow + 64][lc4], &Bbase[(size_t)(lrow + 64) * K + k0 + lc4]);
    };

    issue(0, 0);
    asm volatile("cp.async.commit_group;");

    for (int it = 0; it < NIT; it++) {
        if (it + 1 < NIT) {
            issue((it + 1) & 1, (it + 1) * BK);
            asm volatile("cp.async.commit_group;");
            asm volatile("cp.async.wait_group 1;");
        } else {
            asm volatile("cp.async.wait_group 0;");
        }
        __syncthreads();

        const int s = it & 1;
#pragma unroll
        for (int ks = 0; ks < BK; ks += 8) {
            uint32_t af[4][4];
#pragma unroll
            for (int mf = 0; mf < 4; mf++) {
                int rb = wm + mf * 16;
                af[mf][0] = f2tf32(As[s][rb + g][ks + t]);
                af[mf][1] = f2tf32(As[s][rb + g + 8][ks + t]);
                af[mf][2] = f2tf32(As[s][rb + g][ks + t + 4]);
                af[mf][3] = f2tf32(As[s][rb + g + 8][ks + t + 4]);
            }
            uint32_t bf[4][2];
#pragma unroll
            for (int nf = 0; nf < 4; nf++) {
                int rb = wn + nf * 8;
                bf[nf][0] = f2tf32(Bs[s][rb + g][ks + t]);
                bf[nf][1] = f2tf32(Bs[s][rb + g][ks + t + 4]);
            }
#pragma unroll
            for (int mf = 0; mf < 4; mf++)
#pragma unroll
                for (int nf = 0; nf < 4; nf++)
                    mma_tf32(acc[mf][nf], af[mf], bf[nf]);
        }
        __syncthreads();
    }

    // epilogue: add bias, store
#pragma unroll
    for (int mf = 0; mf < 4; mf++) {
#pragma unroll
        for (int nf = 0; nf < 4; nf++) {
            int row0 = bm + wm + mf * 16 + g;
            int col  = bn + wn + nf * 8 + 2 * t;
            float b0 = bias[col], b1 = bias[col + 1];
            float2 o0 = {acc[mf][nf][0] + b0, acc[mf][nf][1] + b1};
            float2 o1 = {acc[mf][nf][2] + b0, acc[mf][nf][3] + b1};
            *(float2*)&C[(size_t)row0 * N + col]       = o0;
            *(float2*)&C[(size_t)(row0 + 8) * N + col] = o1;
        }
    }
}

// ---------------- fused cosine attention per (window, head) ----------------
__global__ __launch_bounds__(256)
void attn_kernel(const float* __restrict__ qkv,       // [MTOT, 1536]
                 const float* __restrict__ mask,      // [256, 64, 64]
                 const float* __restrict__ logit_scale, // [16]
                 const float* __restrict__ bias,      // [16, 64, 64]
                 float* __restrict__ out)             // [MTOT, 512]
{
    __shared__ float qs[NTOK][HDIM + 1];
    __shared__ float ks[NTOK][HDIM + 1];
    __shared__ float vs[NTOK][HDIM + 1];
    __shared__ float S[NTOK][NTOK + 1];

    const int w = blockIdx.x;
    const int h = blockIdx.y;
    const int tid = threadIdx.x;

    const float* base = qkv + (size_t)w * NTOK * QKV_N + h * HDIM;

    for (int idx = tid; idx < NTOK * HDIM / 4; idx += 256) {
        int n = idx >> 3;
        int d = (idx & 7) * 4;
        const float* r = base + n * QKV_N + d;
        float4 q4 = *(const float4*)(r);
        float4 k4 = *(const float4*)(r + 512);
        float4 v4 = *(const float4*)(r + 1024);
        qs[n][d] = q4.x; qs[n][d + 1] = q4.y; qs[n][d + 2] = q4.z; qs[n][d + 3] = q4.w;
        ks[n][d] = k4.x; ks[n][d + 1] = k4.y; ks[n][d + 2] = k4.z; ks[n][d + 3] = k4.w;
        vs[n][d] = v4.x; vs[n][d + 1] = v4.y; vs[n][d + 2] = v4.z; vs[n][d + 3] = v4.w;
    }
    __syncthreads();

    const float scale = expf(fminf(logit_scale[h], 4.605170186f)); // ln(100)
    if (tid < 128) {
        int r = tid & 63;
        float* row = (tid < 64) ? qs[r] : ks[r];
        float ss = 0.0f;
#pragma unroll
        for (int d = 0; d < HDIM; d++) ss += row[d] * row[d];
        float rn = rsqrtf(ss);
        if (tid < 64) rn *= scale;
#pragma unroll
        for (int d = 0; d < HDIM; d++) row[d] *= rn;
    }
    __syncthreads();

    {
        const int i = tid >> 2;
        const int jb = (tid & 3) * 16;
        const float* bh = bias + h * 4096 + i * 64;
        const float* mh = mask + (size_t)(w & (NUM_WIN - 1)) * 4096 + i * 64;
#pragma unroll
        for (int j = 0; j < 16; j++) {
            float dot = 0.0f;
#pragma unroll
            for (int d = 0; d < HDIM; d++) dot = fmaf(qs[i][d], ks[jb + j][d], dot);
            S[i][jb + j] = dot + bh[jb + j] + mh[jb + j];
        }
    }
    __syncthreads();

    if (tid < NTOK) {
        float mx = -1e30f;
#pragma unroll
        for (int j = 0; j < NTOK; j++) mx = fmaxf(mx, S[tid][j]);
        float sum = 0.0f;
#pragma unroll
        for (int j = 0; j < NTOK; j++) {
            float e = expf(S[tid][j] - mx);
            S[tid][j] = e;
            sum += e;
        }
        float inv = 1.0f / sum;
#pragma unroll
        for (int j = 0; j < NTOK; j++) S[tid][j] *= inv;
    }
    __syncthreads();

    {
        const int i = tid >> 2;
        const int db = (tid & 3) * 8;
        float o[8];
#pragma unroll
        for (int d = 0; d < 8; d++) o[d] = 0.0f;
#pragma unroll
        for (int m = 0; m < NTOK; m++) {
            float s = S[i][m];
#pragma unroll
            for (int d = 0; d < 8; d++) o[d] = fmaf(s, vs[m][db + d], o[d]);
        }
        float* op = out + (size_t)(w * NTOK + i) * CDIM + h * HDIM + db;
        float4 o0 = {o[0], o[1], o[2], o[3]};
        float4 o1 = {o[4], o[5], o[6], o[7]};
        *(float4*)(op)     = o0;
        *(float4*)(op + 4) = o1;
    }
}

// ---------------- launch ----------------
extern "C" void kernel_launch(void* const* d_in, const int* in_sizes, int n_in,
                              void* d_out, int out_size)
{
    const float* x           = (const float*)d_in[0];
    const float* mask        = (const float*)d_in[1];
    const float* qkv_w       = (const float*)d_in[2];
    const float* q_bias      = (const float*)d_in[3];
    const float* v_bias      = (const float*)d_in[4];
    const float* logit_scale = (const float*)d_in[5];
    const float* cpb_w1      = (const float*)d_in[6];
    const float* cpb_b1      = (const float*)d_in[7];
    const float* cpb_w2      = (const float*)d_in[8];
    const float* proj_w      = (const float*)d_in[9];
    const float* proj_b      = (const float*)d_in[10];
    float* out = (float*)d_out;

    float *qkv_buf, *attn_buf, *bias_buf, *qb_buf;
    cudaGetSymbolAddress((void**)&qkv_buf, g_qkv);
    cudaGetSymbolAddress((void**)&attn_buf, g_attn);
    cudaGetSymbolAddress((void**)&bias_buf, g_bias);
    cudaGetSymbolAddress((void**)&qb_buf, g_qkvbias);

    qkvbias_kernel<<<(QKV_N + 255) / 256, 256>>>(q_bias, v_bias, qb_buf);
    cpb_bias_kernel<<<NHEAD, 256>>>(cpb_w1, cpb_b1, cpb_w2, bias_buf);

    // QKV projection: [262144,512] @ [1536,512]^T
    {
        dim3 grid(QKV_N / BN, MTOT / BM);
        mma_gemm_bias<<<grid, 256>>>(x, qkv_w, qb_buf, qkv_buf,
                                     MTOT, QKV_N, CDIM);
    }

    // attention
    {
        dim3 grid(B_WIN, NHEAD);
        attn_kernel<<<grid, 256>>>(qkv_buf, mask, logit_scale, bias_buf, attn_buf);
    }

    // output projection: [262144,512] @ [512,512]^T -> d_out
    {
        dim3 grid(CDIM / BN, MTOT / BM);
        mma_gemm_bias<<<grid, 256>>>(attn_buf, proj_w, proj_b, out,
                                     MTOT, CDIM, CDIM);
    }
}